// round 7
// baseline (speedup 1.0000x reference)
#include <cuda_runtime.h>
#include <math.h>

// Geometry: 64 images of 512*512*3 = 786432 floats (3 MB each)
#define N_IMG 64
#define IMG_ELEMS 786432
#define IMG_VEC4  196608               // IMG_ELEMS / 4
#define BLOCKS_PER_IMG 24
#define NBLK (N_IMG * BLOCKS_PER_IMG)             // 1536
#define CHUNK_VEC4 (IMG_VEC4 / BLOCKS_PER_IMG)    // 8192
#define RED_THREADS 256

// Scratch (no allocations allowed)
__device__ float2 g_partials[N_IMG * BLOCKS_PER_IMG];

// -------- Kernel 1: per-chunk partial (sum, sumsq); forward stride fills L2 --------
__global__ __launch_bounds__(RED_THREADS)
void partial_reduce_kernel(const float4* __restrict__ in) {
    const int img   = blockIdx.x / BLOCKS_PER_IMG;
    const int chunk = blockIdx.x % BLOCKS_PER_IMG;
    const float4* __restrict__ p =
        in + (size_t)img * IMG_VEC4 + (size_t)chunk * CHUNK_VEC4;

    float s = 0.f, sq = 0.f;
    #pragma unroll 8
    for (int i = threadIdx.x; i < CHUNK_VEC4; i += RED_THREADS) {
        float4 v = __ldcg(p + i);          // cache in L2 (re-read by apply)
        s  += (v.x + v.y) + (v.z + v.w);
        sq += (v.x * v.x + v.y * v.y) + (v.z * v.z + v.w * v.w);
    }

    #pragma unroll
    for (int off = 16; off > 0; off >>= 1) {
        s  += __shfl_down_sync(0xffffffffu, s,  off);
        sq += __shfl_down_sync(0xffffffffu, sq, off);
    }
    __shared__ float2 warp_red[RED_THREADS / 32];
    const int lane = threadIdx.x & 31, wid = threadIdx.x >> 5;
    if (lane == 0) warp_red[wid] = make_float2(s, sq);
    __syncthreads();
    if (wid == 0) {
        float2 v = (lane < RED_THREADS / 32) ? warp_red[lane] : make_float2(0.f, 0.f);
        s = v.x; sq = v.y;
        #pragma unroll
        for (int off = 4; off > 0; off >>= 1) {
            s  += __shfl_down_sync(0xffffffffu, s,  off);
            sq += __shfl_down_sync(0xffffffffu, sq, off);
        }
        if (lane == 0) g_partials[blockIdx.x] = make_float2(s, sq);
    }
}

// -------- Kernel 2: apply, mirroring kernel 1's access pattern in reverse --------
// Same grid shape as the reduce; each block walks ITS chunk backwards so the
// first loads touch the most-recently-cached lines (chunk tails). Block ids
// are mirrored so apply wave-1 covers reduce wave-2 (globally freshest chunks).
// All accesses evict-first: lines are touched once; caching fills would only
// evict the residue before we reach it.
__global__ __launch_bounds__(RED_THREADS)
void apply_kernel(const float4* __restrict__ in, float4* __restrict__ out) {
    const int blk   = (NBLK - 1) - blockIdx.x;
    const int img   = blk / BLOCKS_PER_IMG;
    const int chunk = blk % BLOCKS_PER_IMG;
    const size_t base = (size_t)img * IMG_VEC4 + (size_t)chunk * CHUNK_VEC4;

    // Inline finalize: warp 0 reduces this image's 24 partials (fixed-order
    // tree -> deterministic, identical across all blocks of the image).
    __shared__ float2 sh_ss;
    if (threadIdx.x < 32) {
        const int lane = threadIdx.x;
        float s = 0.f, sq = 0.f;
        if (lane < BLOCKS_PER_IMG) {
            float2 p = g_partials[img * BLOCKS_PER_IMG + lane];
            s = p.x; sq = p.y;
        }
        #pragma unroll
        for (int off = 16; off > 0; off >>= 1) {
            s  += __shfl_down_sync(0xffffffffu, s,  off);
            sq += __shfl_down_sync(0xffffffffu, sq, off);
        }
        if (lane == 0) {
            const float inv_n = 1.0f / (float)IMG_ELEMS;
            float mean = s * inv_n;
            float var  = sq * inv_n - mean * mean;
            float stddev = sqrtf(fmaxf(var, 0.0f));
            const float min_std = 1.0f / sqrtf((float)IMG_ELEMS);
            float scale = 1.0f / fmaxf(stddev, min_std);
            sh_ss = make_float2(scale, -mean * scale);
        }
    }
    __syncthreads();
    const float scale = sh_ss.x, shift = sh_ss.y;

    // Reverse intra-chunk walk: i descends; lanes ascend -> coalesced.
    #pragma unroll 8
    for (int i = (CHUNK_VEC4 - RED_THREADS) + (int)threadIdx.x; i >= 0; i -= RED_THREADS) {
        float4 v = __ldcs(in + base + i);
        float4 r;
        r.x = fmaf(v.x, scale, shift);
        r.y = fmaf(v.y, scale, shift);
        r.z = fmaf(v.z, scale, shift);
        r.w = fmaf(v.w, scale, shift);
        __stcs(out + base + i, r);
    }
}

extern "C" void kernel_launch(void* const* d_in, const int* in_sizes, int n_in,
                              void* d_out, int out_size) {
    const float4* in = (const float4*)d_in[0];
    float4* out = (float4*)d_out;

    partial_reduce_kernel<<<NBLK, RED_THREADS>>>(in);
    apply_kernel<<<NBLK, RED_THREADS>>>(in, out);
}

// round 10
// speedup vs baseline: 1.1351x; 1.1351x over previous
#include <cuda_runtime.h>
#include <math.h>

// Geometry: 64 images of 512*512*3 = 786432 floats (3 MB each)
#define N_IMG 64
#define IMG_ELEMS 786432
#define IMG_VEC4  196608                 // IMG_ELEMS / 4

#define GROUPS 4
#define IMG_PER_GRP 16                   // 48 MB per group << 126 MB L2

// Reduce shape (per group)
#define BLOCKS_PER_IMG 24
#define CHUNK_VEC4 (IMG_VEC4 / BLOCKS_PER_IMG)          // 8192
#define RED_THREADS 256
#define RED_BLOCKS (IMG_PER_GRP * BLOCKS_PER_IMG)       // 384

// Apply shape (per group) — R6's best config
#define APPLY_THREADS 256
#define V4_PER_THREAD 4
#define V4_PER_BLOCK (APPLY_THREADS * V4_PER_THREAD)    // 1024
#define APPLY_BLOCKS_PER_IMG (IMG_VEC4 / V4_PER_BLOCK)  // 192
#define APPLY_BLOCKS (IMG_PER_GRP * APPLY_BLOCKS_PER_IMG) // 3072

// Scratch (no allocations allowed)
__device__ float2 g_partials[N_IMG * BLOCKS_PER_IMG];

// -------- Reduce one group: per-chunk (sum, sumsq); fills L2 with the group --------
__global__ __launch_bounds__(RED_THREADS)
void partial_reduce_kernel(const float4* __restrict__ in, int grp) {
    const int limg  = blockIdx.x / BLOCKS_PER_IMG;
    const int chunk = blockIdx.x % BLOCKS_PER_IMG;
    const int img   = grp * IMG_PER_GRP + limg;
    const float4* __restrict__ p =
        in + (size_t)img * IMG_VEC4 + (size_t)chunk * CHUNK_VEC4;

    float s = 0.f, sq = 0.f;
    #pragma unroll 8
    for (int i = threadIdx.x; i < CHUNK_VEC4; i += RED_THREADS) {
        float4 v = __ldcg(p + i);          // evict-normal in L2: apply re-reads it
        s  += (v.x + v.y) + (v.z + v.w);
        sq += (v.x * v.x + v.y * v.y) + (v.z * v.z + v.w * v.w);
    }

    #pragma unroll
    for (int off = 16; off > 0; off >>= 1) {
        s  += __shfl_down_sync(0xffffffffu, s,  off);
        sq += __shfl_down_sync(0xffffffffu, sq, off);
    }
    __shared__ float2 warp_red[RED_THREADS / 32];
    const int lane = threadIdx.x & 31, wid = threadIdx.x >> 5;
    if (lane == 0) warp_red[wid] = make_float2(s, sq);
    __syncthreads();
    if (wid == 0) {
        float2 v = (lane < RED_THREADS / 32) ? warp_red[lane] : make_float2(0.f, 0.f);
        s = v.x; sq = v.y;
        #pragma unroll
        for (int off = 4; off > 0; off >>= 1) {
            s  += __shfl_down_sync(0xffffffffu, s,  off);
            sq += __shfl_down_sync(0xffffffffu, sq, off);
        }
        if (lane == 0) g_partials[img * BLOCKS_PER_IMG + chunk] = make_float2(s, sq);
    }
}

// -------- Apply one group: reads come from L2 (group just streamed by reduce) --------
__global__ __launch_bounds__(APPLY_THREADS)
void apply_kernel(const float4* __restrict__ in, float4* __restrict__ out, int grp) {
    const int limg = blockIdx.x / APPLY_BLOCKS_PER_IMG;
    const int img  = grp * IMG_PER_GRP + limg;
    const size_t base = (size_t)img * IMG_VEC4 +
                        (size_t)(blockIdx.x % APPLY_BLOCKS_PER_IMG) * V4_PER_BLOCK +
                        threadIdx.x;

    // Front-batch loads: mostly L2 hits; .cs marks lines dead after read.
    float4 v[V4_PER_THREAD];
    #pragma unroll
    for (int k = 0; k < V4_PER_THREAD; ++k)
        v[k] = __ldcs(in + base + k * APPLY_THREADS);

    // Inline finalize: warp 0 reduces this image's 24 partials (fixed-order
    // tree -> deterministic, identical across all blocks of the image).
    __shared__ float2 sh_ss;
    if (threadIdx.x < 32) {
        const int lane = threadIdx.x;
        float s = 0.f, sq = 0.f;
        if (lane < BLOCKS_PER_IMG) {
            float2 p = g_partials[img * BLOCKS_PER_IMG + lane];
            s = p.x; sq = p.y;
        }
        #pragma unroll
        for (int off = 16; off > 0; off >>= 1) {
            s  += __shfl_down_sync(0xffffffffu, s,  off);
            sq += __shfl_down_sync(0xffffffffu, sq, off);
        }
        if (lane == 0) {
            const float inv_n = 1.0f / (float)IMG_ELEMS;
            float mean = s * inv_n;
            float var  = sq * inv_n - mean * mean;
            float stddev = sqrtf(fmaxf(var, 0.0f));
            const float min_std = 1.0f / sqrtf((float)IMG_ELEMS);
            float scale = 1.0f / fmaxf(stddev, min_std);
            sh_ss = make_float2(scale, -mean * scale);
        }
    }
    __syncthreads();
    const float scale = sh_ss.x, shift = sh_ss.y;

    #pragma unroll
    for (int k = 0; k < V4_PER_THREAD; ++k) {
        float4 r;
        r.x = fmaf(v[k].x, scale, shift);
        r.y = fmaf(v[k].y, scale, shift);
        r.z = fmaf(v[k].z, scale, shift);
        r.w = fmaf(v[k].w, scale, shift);
        __stcs(out + base + k * APPLY_THREADS, r);   // evict-first: spare the residue
    }
}

extern "C" void kernel_launch(void* const* d_in, const int* in_sizes, int n_in,
                              void* d_out, int out_size) {
    const float4* in = (const float4*)d_in[0];
    float4* out = (float4*)d_out;

    for (int g = 0; g < GROUPS; ++g) {
        partial_reduce_kernel<<<RED_BLOCKS, RED_THREADS>>>(in, g);
        apply_kernel<<<APPLY_BLOCKS, APPLY_THREADS>>>(in, out, g);
    }
}